// round 5
// baseline (speedup 1.0000x reference)
#include <cuda_runtime.h>
#include <math.h>

#define EPS 1e-5f
typedef unsigned long long ull;

// ---------------- f32x2 packed helpers ----------------
__device__ __forceinline__ ull pk2(float lo, float hi) {
    ull r; asm("mov.b64 %0,{%1,%2};" : "=l"(r) : "f"(lo), "f"(hi)); return r;
}
__device__ __forceinline__ void unpk2(float& lo, float& hi, ull v) {
    asm("mov.b64 {%0,%1},%2;" : "=f"(lo), "=f"(hi) : "l"(v));
}
__device__ __forceinline__ ull fma2(ull a, ull b, ull c) {
    ull d; asm("fma.rn.f32x2 %0,%1,%2,%3;" : "=l"(d) : "l"(a), "l"(b), "l"(c)); return d;
}
__device__ __forceinline__ ull add2(ull a, ull b) {
    ull d; asm("add.rn.f32x2 %0,%1,%2;" : "=l"(d) : "l"(a), "l"(b)); return d;
}

// ---------------- scratch (device globals; no allocations) ----------------
__device__ float g_xn[512 * 768];
__device__ float g_qkv[512 * 2304];
__device__ float g_qh[12 * 512 * 64];    // [h][i][d], q * scale
__device__ float g_kT[12 * 64 * 512];    // [h][d][j]
__device__ float g_vh[12 * 512 * 64];    // [h][j][d]
__device__ float g_gW[768 * 12];         // pair_g[c] * Wbias[c][h]
__device__ float g_GW[12];
__device__ float g_BW[12];
__device__ float g_bias[12 * 512 * 512]; // [h][i][j]; j>i stays 0 (.bss)
__device__ float g_sim[12 * 512 * 512];  // [h][i][j], reused as attn
__device__ float g_attout[512 * 768];    // [i][h*64+d]

// ---------------- precompute gW, GW, BW ----------------
__global__ void precompute_gw(const float* __restrict__ pg,
                              const float* __restrict__ pb,
                              const float* __restrict__ Wb) {
    int t = threadIdx.x; // 384
    for (int idx = t; idx < 768 * 12; idx += 384)
        g_gW[idx] = pg[idx / 12] * Wb[idx];
    int w = t >> 5, l = t & 31;
    if (w < 12) {
        float gw = 0.f, bw = 0.f;
        for (int c = l; c < 768; c += 32) {
            float wv = Wb[c * 12 + w];
            gw = fmaf(pg[c], wv, gw);
            bw = fmaf(pb[c], wv, bw);
        }
#pragma unroll
        for (int o = 16; o; o >>= 1) {
            gw += __shfl_xor_sync(0xffffffffu, gw, o);
            bw += __shfl_xor_sync(0xffffffffu, bw, o);
        }
        if (l == 0) { g_GW[w] = gw; g_BW[w] = bw; }
    }
}

// ---------------- LN(x) -> g_xn ----------------
__global__ void __launch_bounds__(192) ln_x_kernel(const float* __restrict__ x,
                                                   const float* __restrict__ g,
                                                   const float* __restrict__ b) {
    int i = blockIdx.x, t = threadIdx.x;
    int c = t * 4;
    float4 xv = *(const float4*)(x + i * 768 + c);
    float s = xv.x + xv.y + xv.z + xv.w;
    float ss = xv.x * xv.x + xv.y * xv.y + xv.z * xv.z + xv.w * xv.w;
    int lane = t & 31, w = t >> 5;
#pragma unroll
    for (int o = 16; o; o >>= 1) {
        s += __shfl_xor_sync(0xffffffffu, s, o);
        ss += __shfl_xor_sync(0xffffffffu, ss, o);
    }
    __shared__ float sh[6][2];
    if (lane == 0) { sh[w][0] = s; sh[w][1] = ss; }
    __syncthreads();
    float S = 0.f, SS = 0.f;
#pragma unroll
    for (int q = 0; q < 6; q++) { S += sh[q][0]; SS += sh[q][1]; }
    float m = S * (1.f / 768.f);
    float r = rsqrtf(SS * (1.f / 768.f) - m * m + EPS);
    float4 gv = *(const float4*)(g + c);
    float4 bv = *(const float4*)(b + c);
    float4 o;
    o.x = (xv.x - m) * r * gv.x + bv.x;
    o.y = (xv.y - m) * r * gv.y + bv.y;
    o.z = (xv.z - m) * r * gv.z + bv.z;
    o.w = (xv.w - m) * r * gv.w + bv.w;
    *(float4*)(g_xn + i * 768 + c) = o;
}

// ---------------- qkv split: QK-LN + head reshapes ----------------
__global__ void __launch_bounds__(192) qkv_prep_kernel(const float* __restrict__ qg,
                                                       const float* __restrict__ qb,
                                                       const float* __restrict__ kg,
                                                       const float* __restrict__ kb) {
    int i = blockIdx.x, p = blockIdx.y, t = threadIdx.x;
    int c = t * 4;
    const float* row = g_qkv + i * 2304 + p * 768;
    float4 xv = *(const float4*)(row + c);
    int h = c >> 6, d = c & 63;
    if (p == 2) {
        *(float4*)(g_vh + (h * 512 + i) * 64 + d) = xv;
        return;
    }
    float s = xv.x + xv.y + xv.z + xv.w;
    float ss = xv.x * xv.x + xv.y * xv.y + xv.z * xv.z + xv.w * xv.w;
    int lane = t & 31, w = t >> 5;
#pragma unroll
    for (int o = 16; o; o >>= 1) {
        s += __shfl_xor_sync(0xffffffffu, s, o);
        ss += __shfl_xor_sync(0xffffffffu, ss, o);
    }
    __shared__ float sh[6][2];
    if (lane == 0) { sh[w][0] = s; sh[w][1] = ss; }
    __syncthreads();
    float S = 0.f, SS = 0.f;
#pragma unroll
    for (int q = 0; q < 6; q++) { S += sh[q][0]; SS += sh[q][1]; }
    float m = S * (1.f / 768.f);
    float r = rsqrtf(SS * (1.f / 768.f) - m * m + EPS);
    const float* gg = (p == 0) ? qg : kg;
    const float* bb = (p == 0) ? qb : kb;
    float4 gv = *(const float4*)(gg + c);
    float4 bv = *(const float4*)(bb + c);
    float v0 = (xv.x - m) * r * gv.x + bv.x;
    float v1 = (xv.y - m) * r * gv.y + bv.y;
    float v2 = (xv.z - m) * r * gv.z + bv.z;
    float v3 = (xv.w - m) * r * gv.w + bv.w;
    if (p == 0) {
        float4 o = make_float4(v0 * 0.125f, v1 * 0.125f, v2 * 0.125f, v3 * 0.125f);
        *(float4*)(g_qh + (h * 512 + i) * 64 + d) = o;
    } else {
        float* kp = g_kT + h * (64 * 512) + d * 512 + i;
        kp[0] = v0; kp[512] = v1; kp[1024] = v2; kp[1536] = v3;
    }
}

// ---------------- pair-bias: fused LN + @Wbias, tril-only, f32x2 ----------
// writes [h][i][j] via smem staging, coalesced
__global__ void __launch_bounds__(64) pair_bias_kernel(const float* __restrict__ pair) {
    int jg = blockIdx.x;  // 0..7
    int i = blockIdx.y;   // 0..511
    int lives = i - jg * 64 + 1;
    if (lives <= 0) return;
    if (lives > 64) lives = 64;
    int t = threadIdx.x;  // 0..63
    int lane = t & 31, w = t >> 5;
    int c0 = t * 12;

    __shared__ float sGW[12], sBW[12];
    __shared__ float part[2][2][14];
    __shared__ float stage[12][64];
    if (t < 12) { sGW[t] = g_GW[t]; sBW[t] = g_BW[t]; }

    ull wp[12][6];
#pragma unroll
    for (int e = 0; e < 12; e++)
#pragma unroll
        for (int h2 = 0; h2 < 6; h2++)
            wp[e][h2] = *(const ull*)&g_gW[(c0 + e) * 12 + h2 * 2];
    __syncthreads();

    const float* base = pair + ((size_t)i * 512 + jg * 64) * 768 + c0;
    float4 x0 = *(const float4*)base;
    float4 x1 = *(const float4*)(base + 4);
    float4 x2 = *(const float4*)(base + 8);

    for (int jj = 0; jj < lives; jj++) {
        float xs[12] = { x0.x, x0.y, x0.z, x0.w, x1.x, x1.y, x1.z, x1.w,
                         x2.x, x2.y, x2.z, x2.w };
        if (jj + 1 < lives) {
            const float* nb = base + (size_t)(jj + 1) * 768;
            x0 = *(const float4*)nb;
            x1 = *(const float4*)(nb + 4);
            x2 = *(const float4*)(nb + 8);
        }
        float s = 0.f, ss = 0.f;
        ull S2[6] = {0ull, 0ull, 0ull, 0ull, 0ull, 0ull};
#pragma unroll
        for (int e = 0; e < 12; e++) {
            float x = xs[e];
            s += x;
            ss = fmaf(x, x, ss);
            ull xx = pk2(x, x);
#pragma unroll
            for (int h2 = 0; h2 < 6; h2++)
                S2[h2] = fma2(xx, wp[e][h2], S2[h2]);
        }
#pragma unroll
        for (int o = 16; o; o >>= 1) {
            s += __shfl_xor_sync(0xffffffffu, s, o);
            ss += __shfl_xor_sync(0xffffffffu, ss, o);
#pragma unroll
            for (int h2 = 0; h2 < 6; h2++)
                S2[h2] = add2(S2[h2], __shfl_xor_sync(0xffffffffu, S2[h2], o));
        }
        int bsel = jj & 1;
        if (lane == 0) {
#pragma unroll
            for (int h2 = 0; h2 < 6; h2++) {
                float lo, hi; unpk2(lo, hi, S2[h2]);
                part[bsel][w][2 * h2] = lo;
                part[bsel][w][2 * h2 + 1] = hi;
            }
            part[bsel][w][12] = s;
            part[bsel][w][13] = ss;
        }
        __syncthreads();
        if (t < 12) {
            float Sh = part[bsel][0][t] + part[bsel][1][t];
            float sm = part[bsel][0][12] + part[bsel][1][12];
            float sq = part[bsel][0][13] + part[bsel][1][13];
            float m = sm * (1.f / 768.f);
            float r = rsqrtf(sq * (1.f / 768.f) - m * m + EPS);
            stage[t][jj] = r * (Sh - m * sGW[t]) + sBW[t];
        }
    }
    __syncthreads();
    // coalesced flush: [h][i][j]
    if (t < lives) {
        int j = jg * 64 + t;
#pragma unroll
        for (int h = 0; h < 12; h++)
            g_bias[((size_t)h * 512 + i) * 512 + j] = stage[h][t];
    }
}

// ---------------- f32x2 GEMM: dup-B smem, row-paired A ----------------
// THREADS = (BM/TM)*(BN/TN). TM even, TN multiple of 4.
template <int BM, int BN, int TM, int TN>
__device__ __forceinline__ void gemm2_body(const float* __restrict__ A,
                                           const float* __restrict__ B,
                                           float* __restrict__ C,
                                           const float* __restrict__ biasRow,
                                           const float* __restrict__ biasMat,
                                           int K, int lda, int ldb, int ldc) {
    constexpr int THREADS = (BM / TM) * (BN / TN);
    constexpr int NB4 = (8 * BN) / (4 * THREADS);   // float4 per thread for B
    static_assert(8 * BM == 4 * THREADS, "A loader shape");
    __shared__ __align__(16) float As[8][BM];
    __shared__ __align__(16) ull Bs[8][BN];

    int tid = threadIdx.x;
    int tx = tid % (BN / TN), ty = tid / (BN / TN);
    int m0 = blockIdx.y * BM, n0 = blockIdx.x * BN;

    ull acc[TM / 2][TN];
#pragma unroll
    for (int rp = 0; rp < TM / 2; rp++)
#pragma unroll
        for (int c = 0; c < TN; c++) acc[rp][c] = 0ull;

    int ar = tid >> 1, ac = (tid & 1) * 4;
    float4 pa = *(const float4*)(A + (size_t)(m0 + ar) * lda + ac);
    float4 pb[NB4];
#pragma unroll
    for (int q = 0; q < NB4; q++) {
        int flat = tid + q * THREADS;
        int br = flat / (BN / 4), bc = (flat % (BN / 4)) * 4;
        pb[q] = *(const float4*)(B + (size_t)br * ldb + n0 + bc);
    }

    for (int k0 = 0; k0 < K; k0 += 8) {
        __syncthreads();
        As[ac + 0][ar] = pa.x; As[ac + 1][ar] = pa.y;
        As[ac + 2][ar] = pa.z; As[ac + 3][ar] = pa.w;
#pragma unroll
        for (int q = 0; q < NB4; q++) {
            int flat = tid + q * THREADS;
            int br = flat / (BN / 4), bc = (flat % (BN / 4)) * 4;
            Bs[br][bc + 0] = pk2(pb[q].x, pb[q].x);
            Bs[br][bc + 1] = pk2(pb[q].y, pb[q].y);
            Bs[br][bc + 2] = pk2(pb[q].z, pb[q].z);
            Bs[br][bc + 3] = pk2(pb[q].w, pb[q].w);
        }
        __syncthreads();
        if (k0 + 8 < K) {
            pa = *(const float4*)(A + (size_t)(m0 + ar) * lda + k0 + 8 + ac);
#pragma unroll
            for (int q = 0; q < NB4; q++) {
                int flat = tid + q * THREADS;
                int br = flat / (BN / 4), bc = (flat % (BN / 4)) * 4;
                pb[q] = *(const float4*)(B + (size_t)(k0 + 8 + br) * ldb + n0 + bc);
            }
        }
#pragma unroll
        for (int kk = 0; kk < 8; kk++) {
            ull a2[TM / 2], b2[TN];
#pragma unroll
            for (int rp = 0; rp < TM / 2; rp++)
                a2[rp] = *(const ull*)&As[kk][ty * TM + 2 * rp];
#pragma unroll
            for (int c = 0; c < TN; c++)
                b2[c] = Bs[kk][tx * TN + c];
#pragma unroll
            for (int rp = 0; rp < TM / 2; rp++)
#pragma unroll
                for (int c = 0; c < TN; c++)
                    acc[rp][c] = fma2(a2[rp], b2[c], acc[rp][c]);
        }
    }

    float bv[TN];
#pragma unroll
    for (int c = 0; c < TN; c++)
        bv[c] = biasRow ? biasRow[n0 + tx * TN + c] : 0.f;

#pragma unroll
    for (int rp = 0; rp < TM / 2; rp++) {
        int r0 = m0 + ty * TM + 2 * rp;
        float lo[TN], hi[TN];
#pragma unroll
        for (int c = 0; c < TN; c++) {
            unpk2(lo[c], hi[c], acc[rp][c]);
            lo[c] += bv[c]; hi[c] += bv[c];
        }
        if (biasMat) {
            const float* b0 = biasMat + (size_t)r0 * ldc + n0 + tx * TN;
            const float* b1 = b0 + ldc;
#pragma unroll
            for (int c4 = 0; c4 < TN / 4; c4++) {
                float4 m0v = *(const float4*)(b0 + 4 * c4);
                float4 m1v = *(const float4*)(b1 + 4 * c4);
                lo[4*c4+0] += m0v.x; lo[4*c4+1] += m0v.y; lo[4*c4+2] += m0v.z; lo[4*c4+3] += m0v.w;
                hi[4*c4+0] += m1v.x; hi[4*c4+1] += m1v.y; hi[4*c4+2] += m1v.z; hi[4*c4+3] += m1v.w;
            }
        }
        float* c0p = C + (size_t)r0 * ldc + n0 + tx * TN;
        float* c1p = c0p + ldc;
#pragma unroll
        for (int c4 = 0; c4 < TN / 4; c4++) {
            *(float4*)(c0p + 4 * c4) = make_float4(lo[4*c4], lo[4*c4+1], lo[4*c4+2], lo[4*c4+3]);
            *(float4*)(c1p + 4 * c4) = make_float4(hi[4*c4], hi[4*c4+1], hi[4*c4+2], hi[4*c4+3]);
        }
    }
}

__global__ void __launch_bounds__(128) gemm_qkv(const float* __restrict__ W,
                                                const float* __restrict__ bias) {
    gemm2_body<64, 128, 8, 8>(g_xn, W, g_qkv, bias, nullptr, 768, 768, 2304, 2304);
}
__global__ void __launch_bounds__(256) gemm_qk() {
    int h = blockIdx.z;
    gemm2_body<128, 128, 8, 8>(g_qh + h * (512 * 64), g_kT + h * (64 * 512),
                               g_sim + (size_t)h * (512 * 512), nullptr,
                               g_bias + (size_t)h * (512 * 512), 64, 64, 512, 512);
}
__global__ void __launch_bounds__(128) gemm_pv() {
    int h = blockIdx.z;
    gemm2_body<64, 64, 4, 8>(g_sim + (size_t)h * (512 * 512), g_vh + h * (512 * 64),
                             g_attout + h * 64, nullptr, nullptr, 512, 512, 64, 768);
}
__global__ void __launch_bounds__(128) gemm_proj(const float* __restrict__ W,
                                                 const float* __restrict__ bias,
                                                 float* __restrict__ out) {
    gemm2_body<64, 64, 4, 8>(g_attout, W, out, bias, nullptr, 768, 768, 768, 768);
}

// ---------------- softmax: warp per (h,i) row, registers only ----------------
__global__ void __launch_bounds__(256) softmax_kernel() {
    int warp = threadIdx.x >> 5, lane = threadIdx.x & 31;
    int rowid = blockIdx.x * 8 + warp;              // 0..6143
    float* row = g_sim + (size_t)rowid * 512;
    float v[16];
    float4* rp = (float4*)(row + lane * 16);
    float4 r0 = rp[0], r1 = rp[1], r2 = rp[2], r3 = rp[3];
    v[0]=r0.x; v[1]=r0.y; v[2]=r0.z; v[3]=r0.w;
    v[4]=r1.x; v[5]=r1.y; v[6]=r1.z; v[7]=r1.w;
    v[8]=r2.x; v[9]=r2.y; v[10]=r2.z; v[11]=r2.w;
    v[12]=r3.x; v[13]=r3.y; v[14]=r3.z; v[15]=r3.w;
    float m = v[0];
#pragma unroll
    for (int e = 1; e < 16; e++) m = fmaxf(m, v[e]);
#pragma unroll
    for (int o = 16; o; o >>= 1) m = fmaxf(m, __shfl_xor_sync(0xffffffffu, m, o));
    float s = 0.f;
#pragma unroll
    for (int e = 0; e < 16; e++) { v[e] = __expf(v[e] - m); s += v[e]; }
#pragma unroll
    for (int o = 16; o; o >>= 1) s += __shfl_xor_sync(0xffffffffu, s, o);
    float inv = __fdividef(1.f, s);
    rp[0] = make_float4(v[0]*inv, v[1]*inv, v[2]*inv, v[3]*inv);
    rp[1] = make_float4(v[4]*inv, v[5]*inv, v[6]*inv, v[7]*inv);
    rp[2] = make_float4(v[8]*inv, v[9]*inv, v[10]*inv, v[11]*inv);
    rp[3] = make_float4(v[12]*inv, v[13]*inv, v[14]*inv, v[15]*inv);
}

// ---------------- launch ----------------
extern "C" void kernel_launch(void* const* d_in, const int* in_sizes, int n_in,
                              void* d_out, int out_size) {
    int base = n_in - 13;                     // norm_g index (mask-type agnostic)
    const float* x      = (const float*)d_in[0];
    const float* pair   = (const float*)d_in[1];
    const float* norm_g = (const float*)d_in[base + 0];
    const float* norm_b = (const float*)d_in[base + 1];
    const float* Wqkv   = (const float*)d_in[base + 2];
    const float* bqkv   = (const float*)d_in[base + 3];
    const float* qln_g  = (const float*)d_in[base + 4];
    const float* qln_b  = (const float*)d_in[base + 5];
    const float* kln_g  = (const float*)d_in[base + 6];
    const float* kln_b  = (const float*)d_in[base + 7];
    const float* pair_g = (const float*)d_in[base + 8];
    const float* pair_b = (const float*)d_in[base + 9];
    const float* Wbias  = (const float*)d_in[base + 10];
    const float* Wproj  = (const float*)d_in[base + 11];
    const float* bproj  = (const float*)d_in[base + 12];
    float* out = (float*)d_out;

    precompute_gw<<<1, 384>>>(pair_g, pair_b, Wbias);
    pair_bias_kernel<<<dim3(8, 512), 64>>>(pair);
    ln_x_kernel<<<512, 192>>>(x, norm_g, norm_b);
    gemm_qkv<<<dim3(18, 8), 128>>>(Wqkv, bqkv);
    qkv_prep_kernel<<<dim3(512, 3), 192>>>(qln_g, qln_b, kln_g, kln_b);
    gemm_qk<<<dim3(4, 4, 12), 256>>>();
    softmax_kernel<<<768, 256>>>();
    gemm_pv<<<dim3(1, 8, 12), 128>>>();
    gemm_proj<<<dim3(12, 8), 128>>>(Wproj, bproj, out);
}

// round 6
// speedup vs baseline: 1.5590x; 1.5590x over previous
#include <cuda_runtime.h>
#include <math.h>

#define EPS 1e-5f
typedef unsigned long long ull;

// ---------------- f32x2 packed helpers ----------------
__device__ __forceinline__ ull pk2(float lo, float hi) {
    ull r; asm("mov.b64 %0,{%1,%2};" : "=l"(r) : "f"(lo), "f"(hi)); return r;
}
__device__ __forceinline__ void unpk2(float& lo, float& hi, ull v) {
    asm("mov.b64 {%0,%1},%2;" : "=f"(lo), "=f"(hi) : "l"(v));
}
__device__ __forceinline__ ull fma2(ull a, ull b, ull c) {
    ull d; asm("fma.rn.f32x2 %0,%1,%2,%3;" : "=l"(d) : "l"(a), "l"(b), "l"(c)); return d;
}
__device__ __forceinline__ ull add2(ull a, ull b) {
    ull d; asm("add.rn.f32x2 %0,%1,%2;" : "=l"(d) : "l"(a), "l"(b)); return d;
}

// ---------------- scratch (device globals; no allocations) ----------------
__device__ float g_xn[512 * 768];
__device__ float g_qkv[512 * 2304];
__device__ float g_qh[12 * 512 * 64];    // [h][i][d], q * scale
__device__ float g_kT[12 * 64 * 512];    // [h][d][j]
__device__ float g_vh[12 * 512 * 64];    // [h][j][d]
__device__ float g_gW[768 * 12];         // pair_g[c] * Wbias[c][h]
__device__ float g_GW[12];
__device__ float g_BW[12];
__device__ float g_bias[12 * 512 * 512]; // [h][i][j]; j>i stays 0 (.bss)
__device__ float g_sim[12 * 512 * 512];  // [h][i][j], reused as attn
__device__ float g_attout[512 * 768];    // [i][h*64+d]

// ---------------- precompute gW, GW, BW ----------------
__global__ void precompute_gw(const float* __restrict__ pg,
                              const float* __restrict__ pb,
                              const float* __restrict__ Wb) {
    int t = threadIdx.x; // 384
    for (int idx = t; idx < 768 * 12; idx += 384)
        g_gW[idx] = pg[idx / 12] * Wb[idx];
    int w = t >> 5, l = t & 31;
    if (w < 12) {
        float gw = 0.f, bw = 0.f;
        for (int c = l; c < 768; c += 32) {
            float wv = Wb[c * 12 + w];
            gw = fmaf(pg[c], wv, gw);
            bw = fmaf(pb[c], wv, bw);
        }
#pragma unroll
        for (int o = 16; o; o >>= 1) {
            gw += __shfl_xor_sync(0xffffffffu, gw, o);
            bw += __shfl_xor_sync(0xffffffffu, bw, o);
        }
        if (l == 0) { g_GW[w] = gw; g_BW[w] = bw; }
    }
}

// ---------------- LN(x) -> g_xn ----------------
__global__ void __launch_bounds__(192) ln_x_kernel(const float* __restrict__ x,
                                                   const float* __restrict__ g,
                                                   const float* __restrict__ b) {
    int i = blockIdx.x, t = threadIdx.x;
    int c = t * 4;
    float4 xv = *(const float4*)(x + i * 768 + c);
    float s = xv.x + xv.y + xv.z + xv.w;
    float ss = xv.x * xv.x + xv.y * xv.y + xv.z * xv.z + xv.w * xv.w;
    int lane = t & 31, w = t >> 5;
#pragma unroll
    for (int o = 16; o; o >>= 1) {
        s += __shfl_xor_sync(0xffffffffu, s, o);
        ss += __shfl_xor_sync(0xffffffffu, ss, o);
    }
    __shared__ float sh[6][2];
    if (lane == 0) { sh[w][0] = s; sh[w][1] = ss; }
    __syncthreads();
    float S = 0.f, SS = 0.f;
#pragma unroll
    for (int q = 0; q < 6; q++) { S += sh[q][0]; SS += sh[q][1]; }
    float m = S * (1.f / 768.f);
    float r = rsqrtf(SS * (1.f / 768.f) - m * m + EPS);
    float4 gv = *(const float4*)(g + c);
    float4 bv = *(const float4*)(b + c);
    float4 o;
    o.x = (xv.x - m) * r * gv.x + bv.x;
    o.y = (xv.y - m) * r * gv.y + bv.y;
    o.z = (xv.z - m) * r * gv.z + bv.z;
    o.w = (xv.w - m) * r * gv.w + bv.w;
    *(float4*)(g_xn + i * 768 + c) = o;
}

// ---------------- qkv split: QK-LN + head reshapes ----------------
__global__ void __launch_bounds__(192) qkv_prep_kernel(const float* __restrict__ qg,
                                                       const float* __restrict__ qb,
                                                       const float* __restrict__ kg,
                                                       const float* __restrict__ kb) {
    int i = blockIdx.x, p = blockIdx.y, t = threadIdx.x;
    int c = t * 4;
    const float* row = g_qkv + i * 2304 + p * 768;
    float4 xv = *(const float4*)(row + c);
    int h = c >> 6, d = c & 63;
    if (p == 2) {
        *(float4*)(g_vh + (h * 512 + i) * 64 + d) = xv;
        return;
    }
    float s = xv.x + xv.y + xv.z + xv.w;
    float ss = xv.x * xv.x + xv.y * xv.y + xv.z * xv.z + xv.w * xv.w;
    int lane = t & 31, w = t >> 5;
#pragma unroll
    for (int o = 16; o; o >>= 1) {
        s += __shfl_xor_sync(0xffffffffu, s, o);
        ss += __shfl_xor_sync(0xffffffffu, ss, o);
    }
    __shared__ float sh[6][2];
    if (lane == 0) { sh[w][0] = s; sh[w][1] = ss; }
    __syncthreads();
    float S = 0.f, SS = 0.f;
#pragma unroll
    for (int q = 0; q < 6; q++) { S += sh[q][0]; SS += sh[q][1]; }
    float m = S * (1.f / 768.f);
    float r = rsqrtf(SS * (1.f / 768.f) - m * m + EPS);
    const float* gg = (p == 0) ? qg : kg;
    const float* bb = (p == 0) ? qb : kb;
    float4 gv = *(const float4*)(gg + c);
    float4 bv = *(const float4*)(bb + c);
    float v0 = (xv.x - m) * r * gv.x + bv.x;
    float v1 = (xv.y - m) * r * gv.y + bv.y;
    float v2 = (xv.z - m) * r * gv.z + bv.z;
    float v3 = (xv.w - m) * r * gv.w + bv.w;
    if (p == 0) {
        float4 o = make_float4(v0 * 0.125f, v1 * 0.125f, v2 * 0.125f, v3 * 0.125f);
        *(float4*)(g_qh + (h * 512 + i) * 64 + d) = o;
    } else {
        float* kp = g_kT + h * (64 * 512) + d * 512 + i;
        kp[0] = v0; kp[512] = v1; kp[1024] = v2; kp[1536] = v3;
    }
}

// ---------------- pair-bias: LN + @Wbias fused, tril-only, barrier-free rows
__global__ void __launch_bounds__(64) pair_bias_kernel(const float* __restrict__ pair) {
    int jg = blockIdx.x;  // 0..7
    int i = blockIdx.y;   // 0..511
    int lives = i - jg * 64 + 1;
    if (lives <= 0) return;
    if (lives > 64) lives = 64;
    int t = threadIdx.x;  // 0..63
    int lane = t & 31, w = t >> 5;
    int c0 = t * 12;

    __shared__ float sGW[12], sBW[12];
    __shared__ float stg[2][64][17];   // [warp][row][12 S + s + ss], padded
    if (t < 12) { sGW[t] = g_GW[t]; sBW[t] = g_BW[t]; }

    ull wp[12][6];
#pragma unroll
    for (int e = 0; e < 12; e++)
#pragma unroll
        for (int h2 = 0; h2 < 6; h2++)
            wp[e][h2] = *(const ull*)&g_gW[(c0 + e) * 12 + h2 * 2];

    const float* base = pair + ((size_t)i * 512 + jg * 64) * 768 + c0;
    float4 x0 = *(const float4*)base;
    float4 x1 = *(const float4*)(base + 4);
    float4 x2 = *(const float4*)(base + 8);

    for (int jj = 0; jj < lives; jj++) {
        float xs[12] = { x0.x, x0.y, x0.z, x0.w, x1.x, x1.y, x1.z, x1.w,
                         x2.x, x2.y, x2.z, x2.w };
        if (jj + 1 < lives) {
            const float* nb = base + (size_t)(jj + 1) * 768;
            x0 = *(const float4*)nb;
            x1 = *(const float4*)(nb + 4);
            x2 = *(const float4*)(nb + 8);
        }
        float s = 0.f, ss = 0.f;
        ull S2[6] = {0ull, 0ull, 0ull, 0ull, 0ull, 0ull};
#pragma unroll
        for (int e = 0; e < 12; e++) {
            float x = xs[e];
            s += x;
            ss = fmaf(x, x, ss);
            ull xx = pk2(x, x);
#pragma unroll
            for (int h2 = 0; h2 < 6; h2++)
                S2[h2] = fma2(xx, wp[e][h2], S2[h2]);
        }
#pragma unroll
        for (int o = 16; o; o >>= 1) {
            s += __shfl_xor_sync(0xffffffffu, s, o);
            ss += __shfl_xor_sync(0xffffffffu, ss, o);
#pragma unroll
            for (int h2 = 0; h2 < 6; h2++)
                S2[h2] = add2(S2[h2], __shfl_xor_sync(0xffffffffu, S2[h2], o));
        }
        if (lane == 0) {
#pragma unroll
            for (int h2 = 0; h2 < 6; h2++) {
                float lo, hi; unpk2(lo, hi, S2[h2]);
                stg[w][jj][2 * h2] = lo;
                stg[w][jj][2 * h2 + 1] = hi;
            }
            stg[w][jj][12] = s;
            stg[w][jj][13] = ss;
        }
    }
    __syncthreads();
    if (t < lives) {
        float sm = stg[0][t][12] + stg[1][t][12];
        float sq = stg[0][t][13] + stg[1][t][13];
        float m = sm * (1.f / 768.f);
        float r = rsqrtf(sq * (1.f / 768.f) - m * m + EPS);
        size_t jpos = (size_t)i * 512 + jg * 64 + t;
#pragma unroll
        for (int h = 0; h < 12; h++) {
            float Sh = stg[0][t][h] + stg[1][t][h];
            g_bias[(size_t)h * (512 * 512) + jpos] = r * (Sh - m * sGW[h]) + sBW[h];
        }
    }
}

// ---------------- f32x2 GEMM: N-packed acc, double-buffered smem ----------
// THREADS = (BM/TM)*(BN/TN) = 256. TM == 4. TN in {4, 8}.
template <int BM, int BN, int TM, int TN>
__device__ __forceinline__ void gemm2_body(const float* __restrict__ A,
                                           const float* __restrict__ B,
                                           float* __restrict__ C,
                                           const float* __restrict__ biasRow,
                                           const float* __restrict__ biasMat,
                                           int K, int lda, int ldb, int ldc) {
    constexpr int THREADS = (BM / TM) * (BN / TN);
    static_assert(THREADS == 256 && TM == 4, "shape");
    __shared__ __align__(16) float As[2][8][BM];
    __shared__ __align__(16) float Bs[2][8][BN];

    int tid = threadIdx.x;
    int tx = tid % (BN / TN), ty = tid / (BN / TN);
    int m0 = blockIdx.y * BM, n0 = blockIdx.x * BN;

    ull acc[TM][TN / 2];
#pragma unroll
    for (int ii = 0; ii < TM; ii++)
#pragma unroll
        for (int j2 = 0; j2 < TN / 2; j2++) acc[ii][j2] = 0ull;

    bool aact = tid < 2 * BM;
    bool bact = tid < 2 * BN;
    int ar = tid >> 1, ac = (tid & 1) * 4;
    int br = tid / (BN / 4), bc = (tid % (BN / 4)) * 4;

    float4 pa = make_float4(0.f, 0.f, 0.f, 0.f), pb = pa;
    if (aact) pa = *(const float4*)(A + (size_t)(m0 + ar) * lda + ac);
    if (bact) pb = *(const float4*)(B + (size_t)br * ldb + n0 + bc);
    if (aact) {
        As[0][ac + 0][ar] = pa.x; As[0][ac + 1][ar] = pa.y;
        As[0][ac + 2][ar] = pa.z; As[0][ac + 3][ar] = pa.w;
    }
    if (bact) *(float4*)&Bs[0][br][bc] = pb;
    __syncthreads();

    int sb = 0;
    for (int k0 = 0; k0 < K; k0 += 8) {
        bool more = (k0 + 8 < K);
        if (more) {
            if (aact) pa = *(const float4*)(A + (size_t)(m0 + ar) * lda + k0 + 8 + ac);
            if (bact) pb = *(const float4*)(B + (size_t)(k0 + 8 + br) * ldb + n0 + bc);
        }
#pragma unroll
        for (int kk = 0; kk < 8; kk++) {
            float4 av = *(const float4*)&As[sb][kk][ty * TM];
            float a4[4] = {av.x, av.y, av.z, av.w};
            ull b2[TN / 2];
            const ull* bp = (const ull*)&Bs[sb][kk][tx * TN];
#pragma unroll
            for (int j2 = 0; j2 < TN / 2; j2++) b2[j2] = bp[j2];
#pragma unroll
            for (int ii = 0; ii < TM; ii++) {
                ull aa = pk2(a4[ii], a4[ii]);
#pragma unroll
                for (int j2 = 0; j2 < TN / 2; j2++)
                    acc[ii][j2] = fma2(aa, b2[j2], acc[ii][j2]);
            }
        }
        if (more) {
            if (aact) {
                As[sb ^ 1][ac + 0][ar] = pa.x; As[sb ^ 1][ac + 1][ar] = pa.y;
                As[sb ^ 1][ac + 2][ar] = pa.z; As[sb ^ 1][ac + 3][ar] = pa.w;
            }
            if (bact) *(float4*)&Bs[sb ^ 1][br][bc] = pb;
            __syncthreads();
            sb ^= 1;
        }
    }

    float bv[TN];
#pragma unroll
    for (int c = 0; c < TN; c++)
        bv[c] = biasRow ? biasRow[n0 + tx * TN + c] : 0.f;

#pragma unroll
    for (int ii = 0; ii < TM; ii++) {
        int r = m0 + ty * TM + ii;
        float o[TN];
#pragma unroll
        for (int j2 = 0; j2 < TN / 2; j2++) {
            unpk2(o[2 * j2], o[2 * j2 + 1], acc[ii][j2]);
            o[2 * j2] += bv[2 * j2];
            o[2 * j2 + 1] += bv[2 * j2 + 1];
        }
        if (biasMat) {
            const float* bm = biasMat + (size_t)r * ldc + n0 + tx * TN;
#pragma unroll
            for (int c4 = 0; c4 < TN / 4; c4++) {
                float4 mv = *(const float4*)(bm + 4 * c4);
                o[4*c4+0] += mv.x; o[4*c4+1] += mv.y;
                o[4*c4+2] += mv.z; o[4*c4+3] += mv.w;
            }
        }
        float* cp = C + (size_t)r * ldc + n0 + tx * TN;
#pragma unroll
        for (int c4 = 0; c4 < TN / 4; c4++)
            *(float4*)(cp + 4 * c4) = make_float4(o[4*c4], o[4*c4+1], o[4*c4+2], o[4*c4+3]);
    }
}

__global__ void __launch_bounds__(256) gemm_qkv(const float* __restrict__ W,
                                                const float* __restrict__ bias) {
    gemm2_body<64, 64, 4, 4>(g_xn, W, g_qkv, bias, nullptr, 768, 768, 2304, 2304);
}
__global__ void __launch_bounds__(256) gemm_qk() {
    int h = blockIdx.z;
    gemm2_body<64, 128, 4, 8>(g_qh + h * (512 * 64), g_kT + h * (64 * 512),
                              g_sim + (size_t)h * (512 * 512), nullptr,
                              g_bias + (size_t)h * (512 * 512), 64, 64, 512, 512);
}
__global__ void __launch_bounds__(256) gemm_pv() {
    int h = blockIdx.z;
    gemm2_body<64, 64, 4, 4>(g_sim + (size_t)h * (512 * 512), g_vh + h * (512 * 64),
                             g_attout + h * 64, nullptr, nullptr, 512, 512, 64, 768);
}
__global__ void __launch_bounds__(256) gemm_proj(const float* __restrict__ W,
                                                 const float* __restrict__ bias,
                                                 float* __restrict__ out) {
    gemm2_body<64, 64, 4, 4>(g_attout, W, out, bias, nullptr, 768, 768, 768, 768);
}

// ---------------- softmax: warp per (h,i) row, registers only ----------------
__global__ void __launch_bounds__(256) softmax_kernel() {
    int warp = threadIdx.x >> 5, lane = threadIdx.x & 31;
    int rowid = blockIdx.x * 8 + warp;              // 0..6143
    float* row = g_sim + (size_t)rowid * 512;
    float v[16];
    float4* rp = (float4*)(row + lane * 16);
    float4 r0 = rp[0], r1 = rp[1], r2 = rp[2], r3 = rp[3];
    v[0]=r0.x; v[1]=r0.y; v[2]=r0.z; v[3]=r0.w;
    v[4]=r1.x; v[5]=r1.y; v[6]=r1.z; v[7]=r1.w;
    v[8]=r2.x; v[9]=r2.y; v[10]=r2.z; v[11]=r2.w;
    v[12]=r3.x; v[13]=r3.y; v[14]=r3.z; v[15]=r3.w;
    float m = v[0];
#pragma unroll
    for (int e = 1; e < 16; e++) m = fmaxf(m, v[e]);
#pragma unroll
    for (int o = 16; o; o >>= 1) m = fmaxf(m, __shfl_xor_sync(0xffffffffu, m, o));
    float s = 0.f;
#pragma unroll
    for (int e = 0; e < 16; e++) { v[e] = __expf(v[e] - m); s += v[e]; }
#pragma unroll
    for (int o = 16; o; o >>= 1) s += __shfl_xor_sync(0xffffffffu, s, o);
    float inv = __fdividef(1.f, s);
    rp[0] = make_float4(v[0]*inv, v[1]*inv, v[2]*inv, v[3]*inv);
    rp[1] = make_float4(v[4]*inv, v[5]*inv, v[6]*inv, v[7]*inv);
    rp[2] = make_float4(v[8]*inv, v[9]*inv, v[10]*inv, v[11]*inv);
    rp[3] = make_float4(v[12]*inv, v[13]*inv, v[14]*inv, v[15]*inv);
}

// ---------------- launch ----------------
extern "C" void kernel_launch(void* const* d_in, const int* in_sizes, int n_in,
                              void* d_out, int out_size) {
    int base = n_in - 13;                     // norm_g index (mask-type agnostic)
    const float* x      = (const float*)d_in[0];
    const float* pair   = (const float*)d_in[1];
    const float* norm_g = (const float*)d_in[base + 0];
    const float* norm_b = (const float*)d_in[base + 1];
    const float* Wqkv   = (const float*)d_in[base + 2];
    const float* bqkv   = (const float*)d_in[base + 3];
    const float* qln_g  = (const float*)d_in[base + 4];
    const float* qln_b  = (const float*)d_in[base + 5];
    const float* kln_g  = (const float*)d_in[base + 6];
    const float* kln_b  = (const float*)d_in[base + 7];
    const float* pair_g = (const float*)d_in[base + 8];
    const float* pair_b = (const float*)d_in[base + 9];
    const float* Wbias  = (const float*)d_in[base + 10];
    const float* Wproj  = (const float*)d_in[base + 11];
    const float* bproj  = (const float*)d_in[base + 12];
    float* out = (float*)d_out;

    precompute_gw<<<1, 384>>>(pair_g, pair_b, Wbias);
    pair_bias_kernel<<<dim3(8, 512), 64>>>(pair);
    ln_x_kernel<<<512, 192>>>(x, norm_g, norm_b);
    gemm_qkv<<<dim3(36, 8), 256>>>(Wqkv, bqkv);
    qkv_prep_kernel<<<dim3(512, 3), 192>>>(qln_g, qln_b, kln_g, kln_b);
    gemm_qk<<<dim3(4, 8, 12), 256>>>();
    softmax_kernel<<<768, 256>>>();
    gemm_pv<<<dim3(1, 8, 12), 256>>>();
    gemm_proj<<<dim3(12, 8), 256>>>(Wproj, bproj, out);
}